// round 9
// baseline (speedup 1.0000x reference)
#include <cuda_runtime.h>
#include <cuda_bf16.h>
#include <mma.h>
#include <cstdint>

using namespace nvcuda;

// Problem constants
#define BB 4
#define SS 1024
#define DD 4096
#define HH 32
#define HD 128
#define BS (BB*SS)        // 4096 rows
#define NEG_INF (-1e30f)

// ---------------------------------------------------------------------------
// Scratch (__device__ globals; allocation-free rule)
// ---------------------------------------------------------------------------
__device__ float g_q[BS * DD];
__device__ float g_k[BS * DD];
__device__ float g_v[BS * DD];
__device__ float g_attn[BS * DD];
__device__ float g_xh[BS * DD];     // also reused for attn-out split
__device__ float g_xl[BS * DD];
__device__ float g_wqh[DD * DD];
__device__ float g_wql[DD * DD];
__device__ float g_wkh[DD * DD];
__device__ float g_wkl[DD * DD];
__device__ float g_wvh[DD * DD];
__device__ float g_wvl[DD * DD];
__device__ float g_woh[DD * DD];
__device__ float g_wol[DD * DD];

// ---------------------------------------------------------------------------
// cp.async helpers
// ---------------------------------------------------------------------------
__device__ __forceinline__ void cp_async16(void* smem_dst, const void* gsrc) {
    unsigned sa = (unsigned)__cvta_generic_to_shared(smem_dst);
    asm volatile("cp.async.cg.shared.global [%0], [%1], 16;\n" :: "r"(sa), "l"(gsrc));
}
__device__ __forceinline__ void cp_async_commit() {
    asm volatile("cp.async.commit_group;\n");
}
template<int N>
__device__ __forceinline__ void cp_async_wait() {
    asm volatile("cp.async.wait_group %0;\n" :: "n"(N));
}

__device__ __forceinline__ float tf32r(float x) {
    float r;
    asm("cvt.rna.tf32.f32 %0, %1;" : "=f"(r) : "f"(x));
    return r;
}

// ---------------------------------------------------------------------------
// fp32 -> (tf32 hi, tf32 lo) split (elementwise, HBM-bound)
// ---------------------------------------------------------------------------
__global__ __launch_bounds__(256)
void split_kernel(const float* __restrict__ in, float* __restrict__ hi,
                  float* __restrict__ lo, int n4)
{
    const int i = blockIdx.x * blockDim.x + threadIdx.x;
    if (i < n4) {
        float4 v = ((const float4*)in)[i];
        float4 h, l;
        h.x = tf32r(v.x); l.x = tf32r(v.x - h.x);
        h.y = tf32r(v.y); l.y = tf32r(v.y - h.y);
        h.z = tf32r(v.z); l.z = tf32r(v.z - h.z);
        h.w = tf32r(v.w); l.w = tf32r(v.w - h.w);
        ((float4*)hi)[i] = h;
        ((float4*)lo)[i] = l;
    }
}

// ---------------------------------------------------------------------------
// TF32 WMMA GEMM with PRE-SPLIT inputs (no in-loop conversion):
//   C[M,N] = (Ah+Al)[M,K] * (Bh+Bl)[N,K]^T  ~= AhBh + AhBl + AlBh
// CTA tile 128x128, BK=32, 256 threads (8 warps as 2x4, warp tile 64x32).
// 4 smem tiles per stage (Ah/Al/Bh/Bl), cp.async double-buffered.
// Optional fused RoPE epilogue via smem staging.
// ---------------------------------------------------------------------------
#define BK 32
#define BKP 36                    // padded k-stride (floats); 144B, 16B-aligned
#define TILE_BUF (128 * BKP)      // 4608 floats per matrix per stage
#define STAGE_FLOATS (4 * TILE_BUF)
#define STG_STRIDE 132
#define GEMM_SMEM_BYTES (2 * STAGE_FLOATS * 4)   // 147456 B

template<bool ROPE>
__global__ __launch_bounds__(256)
void gemm_tc_kernel(const float* __restrict__ Ah, const float* __restrict__ Al,
                    const float* __restrict__ Bh, const float* __restrict__ Bl,
                    float* __restrict__ C,
                    const float* __restrict__ cosb,
                    const float* __restrict__ sinb)
{
    extern __shared__ float sm[];

    const int tid = threadIdx.x;
    const int wid = tid >> 5;
    const int wm  = wid >> 2;            // 0..1  -> m offset wm*64
    const int wn  = wid & 3;             // 0..3  -> n offset wn*32
    const int m0  = blockIdx.y * 128;
    const int n0  = blockIdx.x * 128;

    wmma::fragment<wmma::accumulator, 16, 16, 8, float> acc[4][2];
    #pragma unroll
    for (int i = 0; i < 4; i++)
        #pragma unroll
        for (int j = 0; j < 2; j++)
            wmma::fill_fragment(acc[i][j], 0.f);

    const int nt = DD / BK;              // 128 k-tiles

    // ---- stage issuer: 4 matrices x 128 rows x 8 float4-chunks
    auto issue = [&](int t) {
        const int buf = t & 1;
        const int k0 = t * BK;
        float* st = sm + buf * STAGE_FLOATS;
        const float* gsrc[4] = { Ah, Al, Bh, Bl };
        const int  gm[4]     = { m0, m0, n0, n0 };
        #pragma unroll
        for (int mtx = 0; mtx < 4; mtx++) {
            float* sdst = st + mtx * TILE_BUF;
            const float* g = gsrc[mtx];
            #pragma unroll
            for (int i = 0; i < 4; i++) {
                const int idx = tid + i * 256;   // 0..1023
                const int r = idx >> 3;
                const int c = (idx & 7) << 2;
                cp_async16(sdst + r * BKP + c,
                           g + (size_t)(gm[mtx] + r) * DD + k0 + c);
            }
        }
    };

    issue(0);
    cp_async_commit();

    for (int t = 0; t < nt; t++) {
        if (t + 1 < nt) {
            issue(t + 1);
            cp_async_commit();
            cp_async_wait<1>();
        } else {
            cp_async_wait<0>();
        }
        __syncthreads();

        const int buf = t & 1;
        const float* sAh = sm + buf * STAGE_FLOATS;
        const float* sAl = sAh + TILE_BUF;
        const float* sBh = sAl + TILE_BUF;
        const float* sBl = sBh + TILE_BUF;

        #pragma unroll
        for (int ks = 0; ks < BK; ks += 8) {
            wmma::fragment<wmma::matrix_a, 16, 16, 8, wmma::precision::tf32, wmma::row_major> ah[4], al[4];
            #pragma unroll
            for (int mm = 0; mm < 4; mm++) {
                const int ro = (wm * 64 + mm * 16) * BKP + ks;
                wmma::load_matrix_sync(ah[mm], sAh + ro, BKP);
                wmma::load_matrix_sync(al[mm], sAl + ro, BKP);
            }
            #pragma unroll
            for (int nn = 0; nn < 2; nn++) {
                wmma::fragment<wmma::matrix_b, 16, 16, 8, wmma::precision::tf32, wmma::col_major> bh, bl;
                const int co = (wn * 32 + nn * 16) * BKP + ks;
                wmma::load_matrix_sync(bh, sBh + co, BKP);
                wmma::load_matrix_sync(bl, sBl + co, BKP);
                #pragma unroll
                for (int mm = 0; mm < 4; mm++) {
                    wmma::mma_sync(acc[mm][nn], ah[mm], bh, acc[mm][nn]);
                    wmma::mma_sync(acc[mm][nn], ah[mm], bl, acc[mm][nn]);
                    wmma::mma_sync(acc[mm][nn], al[mm], bh, acc[mm][nn]);
                }
            }
        }
        __syncthreads();
    }

    // ---- epilogue via smem staging (fragment layout stays opaque)
    float* stg = sm;
    #pragma unroll
    for (int mm = 0; mm < 4; mm++)
        #pragma unroll
        for (int nn = 0; nn < 2; nn++)
            wmma::store_matrix_sync(stg + (wm * 64 + mm * 16) * STG_STRIDE + wn * 32 + nn * 16,
                                    acc[mm][nn], STG_STRIDE, wmma::mem_row_major);
    __syncthreads();

    const int er = tid >> 1;             // 0..127 (row within tile)
    const int ec = (tid & 1) * 64;       // column half
    const int gm = m0 + er;
    const int sp = gm & (SS - 1);
    #pragma unroll
    for (int j = 0; j < 64; j += 4) {
        float4 v = *(const float4*)(stg + er * STG_STRIDE + ec + j);
        if (ROPE) {
            const int col = ec + j;      // head-local (n0 mult of 128 == HD)
            const int pi = col >> 1;
            const float c0 = cosb[sp * (HD / 2) + pi];
            const float s0 = sinb[sp * (HD / 2) + pi];
            const float c1 = cosb[sp * (HD / 2) + pi + 1];
            const float s1 = sinb[sp * (HD / 2) + pi + 1];
            float re = v.x, im = v.y;
            v.x = re * c0 - im * s0;
            v.y = re * s0 + im * c0;
            re = v.z; im = v.w;
            v.z = re * c1 - im * s1;
            v.w = re * s1 + im * c1;
        }
        *(float4*)(C + (size_t)gm * DD + n0 + ec + j) = v;
    }
}

// ---------------------------------------------------------------------------
// Flash attention (causal), fp32 — unchanged (measured 2.0 ms).
// ---------------------------------------------------------------------------
#define QT_STRIDE 65
#define V_STRIDE 132
#define SC_STRIDE 65

__global__ __launch_bounds__(256)
void attn_kernel(const float* __restrict__ Q,
                 const float* __restrict__ K,
                 const float* __restrict__ V,
                 float* __restrict__ O)
{
    extern __shared__ float sma[];
    float* qT   = sma;
    float* kT   = qT + 128 * QT_STRIDE;
    float* vs   = kT + 128 * QT_STRIDE;
    float* sc   = vs + 64 * V_STRIDE;
    float* m_s  = sc + 64 * SC_STRIDE;
    float* l_s  = m_s + 64;
    float* al_s = l_s + 64;

    const int tid = threadIdx.x;
    const int qb  = blockIdx.x;
    const int bh  = blockIdx.y;
    const int b   = bh >> 5;
    const int h   = bh & 31;
    const size_t headoff = (size_t)h * HD;
    const int q0 = qb * 64;

    for (int t = tid; t < 64 * 128; t += 256) {
        const int r = t >> 7, d = t & 127;
        qT[d * QT_STRIDE + r] =
            Q[(size_t)(b * SS + q0 + r) * DD + headoff + d];
    }
    if (tid < 64) { m_s[tid] = NEG_INF; l_s[tid] = 0.f; }

    const int tx = tid & 15, ty = tid >> 4;
    const int r0  = ty * 4;
    const int c0s = tx * 4;

    float o[4][8];
    #pragma unroll
    for (int i = 0; i < 4; i++)
        #pragma unroll
        for (int cc = 0; cc < 8; cc++) o[i][cc] = 0.f;

    const float scale = 0.088388347648318447f;

    for (int kv = 0; kv <= qb; kv++) {
        const int k0r = kv * 64;
        __syncthreads();

        for (int t = tid; t < 64 * 128; t += 256) {
            const int r = t >> 7, d = t & 127;
            const size_t g = (size_t)(b * SS + k0r + r) * DD + headoff + d;
            kT[d * QT_STRIDE + r] = K[g];
            vs[r * V_STRIDE + d]  = V[g];
        }
        __syncthreads();

        float s4[4][4];
        #pragma unroll
        for (int i = 0; i < 4; i++)
            #pragma unroll
            for (int j = 0; j < 4; j++) s4[i][j] = 0.f;

        #pragma unroll 4
        for (int kk = 0; kk < 128; kk++) {
            float a[4], bb2[4];
            #pragma unroll
            for (int i = 0; i < 4; i++) a[i]   = qT[kk * QT_STRIDE + r0 + i];
            #pragma unroll
            for (int j = 0; j < 4; j++) bb2[j] = kT[kk * QT_STRIDE + c0s + j];
            #pragma unroll
            for (int i = 0; i < 4; i++)
                #pragma unroll
                for (int j = 0; j < 4; j++)
                    s4[i][j] += a[i] * bb2[j];
        }
        #pragma unroll
        for (int i = 0; i < 4; i++)
            #pragma unroll
            for (int j = 0; j < 4; j++)
                sc[(r0 + i) * SC_STRIDE + c0s + j] = s4[i][j];
        __syncthreads();

        {
            const int wp = tid >> 5, ln = tid & 31;
            const bool diag = (kv == qb);
            for (int rr = 0; rr < 8; rr++) {
                const int r = wp * 8 + rr;
                const int qidx = q0 + r;
                float v0 = sc[r * SC_STRIDE + ln] * scale;
                float v1 = sc[r * SC_STRIDE + 32 + ln] * scale;
                if (diag) {
                    if (k0r + ln > qidx)      v0 = NEG_INF;
                    if (k0r + 32 + ln > qidx) v1 = NEG_INF;
                }
                float mx = fmaxf(v0, v1);
                #pragma unroll
                for (int off = 16; off; off >>= 1)
                    mx = fmaxf(mx, __shfl_xor_sync(0xffffffffu, mx, off));
                const float mold = m_s[r];
                const float mnew = fmaxf(mold, mx);
                const float p0 = __expf(v0 - mnew);
                const float p1 = __expf(v1 - mnew);
                float sum = p0 + p1;
                #pragma unroll
                for (int off = 16; off; off >>= 1)
                    sum += __shfl_xor_sync(0xffffffffu, sum, off);
                sc[r * SC_STRIDE + ln]      = p0;
                sc[r * SC_STRIDE + 32 + ln] = p1;
                if (ln == 0) {
                    const float alpha = __expf(mold - mnew);
                    al_s[r] = alpha;
                    m_s[r]  = mnew;
                    l_s[r]  = l_s[r] * alpha + sum;
                }
            }
        }
        __syncthreads();

        float a4[4];
        #pragma unroll
        for (int i = 0; i < 4; i++) a4[i] = al_s[r0 + i];
        #pragma unroll
        for (int i = 0; i < 4; i++)
            #pragma unroll
            for (int cc = 0; cc < 8; cc++) o[i][cc] *= a4[i];

        #pragma unroll 2
        for (int j = 0; j < 64; j++) {
            float p[4], vv[8];
            #pragma unroll
            for (int i = 0; i < 4; i++) p[i] = sc[(r0 + i) * SC_STRIDE + j];
            #pragma unroll
            for (int cc = 0; cc < 8; cc++) vv[cc] = vs[j * V_STRIDE + tx + 16 * cc];
            #pragma unroll
            for (int i = 0; i < 4; i++)
                #pragma unroll
                for (int cc = 0; cc < 8; cc++)
                    o[i][cc] += p[i] * vv[cc];
        }
    }

    #pragma unroll
    for (int i = 0; i < 4; i++) {
        const float inv = 1.f / l_s[r0 + i];
        const size_t base = (size_t)(b * SS + q0 + r0 + i) * DD + headoff;
        #pragma unroll
        for (int cc = 0; cc < 8; cc++)
            O[base + tx + 16 * cc] = o[i][cc] * inv;
    }
}

// ---------------------------------------------------------------------------
// kernel_launch
// inputs: 0:x 1:wq 2:wk 3:wv 4:wo 5:freqs_cos 6:freqs_sin 7:mask(unused)
// ---------------------------------------------------------------------------
extern "C" void kernel_launch(void* const* d_in, const int* in_sizes, int n_in,
                              void* d_out, int out_size)
{
    const float* x    = (const float*)d_in[0];
    const float* wq   = (const float*)d_in[1];
    const float* wk   = (const float*)d_in[2];
    const float* wv   = (const float*)d_in[3];
    const float* wo   = (const float*)d_in[4];
    const float* cosb = (const float*)d_in[5];
    const float* sinb = (const float*)d_in[6];
    float* out = (float*)d_out;

    float *pq, *pk, *pv, *pa, *pxh, *pxl;
    float *pwqh, *pwql, *pwkh, *pwkl, *pwvh, *pwvl, *pwoh, *pwol;
    cudaGetSymbolAddress((void**)&pq,  g_q);
    cudaGetSymbolAddress((void**)&pk,  g_k);
    cudaGetSymbolAddress((void**)&pv,  g_v);
    cudaGetSymbolAddress((void**)&pa,  g_attn);
    cudaGetSymbolAddress((void**)&pxh, g_xh);
    cudaGetSymbolAddress((void**)&pxl, g_xl);
    cudaGetSymbolAddress((void**)&pwqh, g_wqh);
    cudaGetSymbolAddress((void**)&pwql, g_wql);
    cudaGetSymbolAddress((void**)&pwkh, g_wkh);
    cudaGetSymbolAddress((void**)&pwkl, g_wkl);
    cudaGetSymbolAddress((void**)&pwvh, g_wvh);
    cudaGetSymbolAddress((void**)&pwvl, g_wvl);
    cudaGetSymbolAddress((void**)&pwoh, g_woh);
    cudaGetSymbolAddress((void**)&pwol, g_wol);

    cudaFuncSetAttribute(gemm_tc_kernel<true>,
                         cudaFuncAttributeMaxDynamicSharedMemorySize, GEMM_SMEM_BYTES);
    cudaFuncSetAttribute(gemm_tc_kernel<false>,
                         cudaFuncAttributeMaxDynamicSharedMemorySize, GEMM_SMEM_BYTES);

    const int attn_smem = (128 * QT_STRIDE * 2 + 64 * V_STRIDE +
                           64 * SC_STRIDE + 3 * 64) * (int)sizeof(float);
    cudaFuncSetAttribute(attn_kernel,
                         cudaFuncAttributeMaxDynamicSharedMemorySize, attn_smem);

    const int n4 = BS * DD / 4;            // 4M float4
    const int sgrid = n4 / 256;            // 16384 blocks

    // splits: x + 4 weights
    split_kernel<<<sgrid, 256>>>(x,  pxh,  pxl,  n4);
    split_kernel<<<sgrid, 256>>>(wq, pwqh, pwql, n4);
    split_kernel<<<sgrid, 256>>>(wk, pwkh, pwkl, n4);
    split_kernel<<<sgrid, 256>>>(wv, pwvh, pwvl, n4);
    split_kernel<<<sgrid, 256>>>(wo, pwoh, pwol, n4);

    dim3 ggrid(DD / 128, BS / 128);        // 32 x 32
    dim3 gblk(256);

    gemm_tc_kernel<true ><<<ggrid, gblk, GEMM_SMEM_BYTES>>>(pxh, pxl, pwqh, pwql, pq, cosb, sinb);
    gemm_tc_kernel<true ><<<ggrid, gblk, GEMM_SMEM_BYTES>>>(pxh, pxl, pwkh, pwkl, pk, cosb, sinb);
    gemm_tc_kernel<false><<<ggrid, gblk, GEMM_SMEM_BYTES>>>(pxh, pxl, pwvh, pwvl, pv, nullptr, nullptr);

    dim3 agrid(SS / 64, BB * HH);          // 16 x 128
    attn_kernel<<<agrid, dim3(256), attn_smem>>>(pq, pk, pv, pa);

    // split attn output (reuse x split buffers) and final projection
    split_kernel<<<sgrid, 256>>>(pa, pxh, pxl, n4);
    gemm_tc_kernel<false><<<ggrid, gblk, GEMM_SMEM_BYTES>>>(pxh, pxl, pwoh, pwol, out, nullptr, nullptr);
}

// round 10
// speedup vs baseline: 1.4271x; 1.4271x over previous
#include <cuda_runtime.h>
#include <cuda_bf16.h>
#include <cstdint>

// Problem constants
#define BB 4
#define SS 1024
#define DD 4096
#define HH 32
#define HD 128
#define BS (BB*SS)        // 4096 rows
#define NEG_INF (-1e30f)

// ---------------------------------------------------------------------------
// Scratch (allocation-free rule: __device__ globals)
// ---------------------------------------------------------------------------
__device__ float g_q[BS * DD];
__device__ float g_k[BS * DD];
__device__ float g_v[BS * DD];
__device__ float g_attn[BS * DD];

// ---------------------------------------------------------------------------
// Packed f32x2 helpers (sm_103 FFMA2 pipe)
// ---------------------------------------------------------------------------
__device__ __forceinline__ unsigned long long pack2_dup(float x) {
    unsigned long long r;
    asm("mov.b64 %0, {%1, %1};" : "=l"(r) : "f"(x));
    return r;
}
__device__ __forceinline__ unsigned long long pack2(float lo, float hi) {
    unsigned long long r;
    asm("mov.b64 %0, {%1, %2};" : "=l"(r) : "f"(lo), "f"(hi));
    return r;
}
__device__ __forceinline__ void unpack2(unsigned long long v, float& lo, float& hi) {
    asm("mov.b64 {%0, %1}, %2;" : "=f"(lo), "=f"(hi) : "l"(v));
}
__device__ __forceinline__ unsigned long long fma2(unsigned long long a,
                                                   unsigned long long b,
                                                   unsigned long long c) {
    unsigned long long d;
    asm("fma.rn.f32x2 %0, %1, %2, %3;" : "=l"(d) : "l"(a), "l"(b), "l"(c));
    return d;
}

// ---------------------------------------------------------------------------
// SGEMM via packed f32x2:  C[M,N] = A[M,K] * W[N,K]^T   (M=N=K=4096)
// 128x128 block tile, BK=8, 256 threads, 8x8 per-thread micro-tile held as
// 8x4 packed f32x2 accumulators (n-pairs). Exact fp32 numerics.
// Optional fused RoPE on the epilogue (for Q/K projections).
// ---------------------------------------------------------------------------
template<bool ROPE>
__global__ __launch_bounds__(256, 2)
void gemm_nt_kernel(const float* __restrict__ A,
                    const float* __restrict__ W,
                    float* __restrict__ C,
                    const float* __restrict__ cosb,
                    const float* __restrict__ sinb)
{
    // stride 132: even (16B-aligned vector loads at multiples of 8 floats),
    // store bank = row mod 32 -> conflict-free stores.
    __shared__ __align__(16) float As[8][132];
    __shared__ __align__(16) float Bs[8][132];

    const int tid = threadIdx.x;
    const int tx  = tid & 15;        // N direction
    const int ty  = tid >> 4;        // M direction
    const int m0  = blockIdx.y * 128;
    const int n0  = blockIdx.x * 128;

    // load mapping: each thread loads one float4 of A and one of W per k-tile
    const int lr = tid >> 1;         // 0..127 (row within tile)
    const int lk = (tid & 1) * 4;    // 0 or 4 (k offset)

    const float* Ap = A + (size_t)(m0 + lr) * DD + lk;
    const float* Wp = W + (size_t)(n0 + lr) * DD + lk;

    unsigned long long acc2[8][4];
    #pragma unroll
    for (int i = 0; i < 8; i++)
        #pragma unroll
        for (int j = 0; j < 4; j++) acc2[i][j] = pack2(0.f, 0.f);

    for (int k0 = 0; k0 < DD; k0 += 8) {
        float4 va = *(const float4*)(Ap + k0);
        float4 vb = *(const float4*)(Wp + k0);
        __syncthreads();               // previous tile consumed
        As[lk + 0][lr] = va.x; As[lk + 1][lr] = va.y;
        As[lk + 2][lr] = va.z; As[lk + 3][lr] = va.w;
        Bs[lk + 0][lr] = vb.x; Bs[lk + 1][lr] = vb.y;
        Bs[lk + 2][lr] = vb.z; Bs[lk + 3][lr] = vb.w;
        __syncthreads();

        #pragma unroll
        for (int kk = 0; kk < 8; kk++) {
            // A: 8 m-values, broadcast-duplicated into packed pairs
            const float4 a0 = *(const float4*)&As[kk][ty * 8];
            const float4 a1 = *(const float4*)&As[kk][ty * 8 + 4];
            unsigned long long pa[8];
            pa[0] = pack2_dup(a0.x); pa[1] = pack2_dup(a0.y);
            pa[2] = pack2_dup(a0.z); pa[3] = pack2_dup(a0.w);
            pa[4] = pack2_dup(a1.x); pa[5] = pack2_dup(a1.y);
            pa[6] = pack2_dup(a1.z); pa[7] = pack2_dup(a1.w);
            // B: 8 n-values as 4 packed pairs (direct 16B shared loads)
            const ulonglong2 b01 = *(const ulonglong2*)&Bs[kk][tx * 8];
            const ulonglong2 b23 = *(const ulonglong2*)&Bs[kk][tx * 8 + 4];
            unsigned long long pb[4] = { b01.x, b01.y, b23.x, b23.y };
            #pragma unroll
            for (int i = 0; i < 8; i++)
                #pragma unroll
                for (int j = 0; j < 4; j++)
                    acc2[i][j] = fma2(pa[i], pb[j], acc2[i][j]);
        }
    }

    // epilogue (+ optional RoPE): row m = b*S + s  ->  s = m & (S-1)
    // acc2[i][j] holds columns (tx*8 + 2j, tx*8 + 2j + 1) — a RoPE (re,im) pair.
    #pragma unroll
    for (int i = 0; i < 8; i++) {
        const int m = m0 + ty * 8 + i;
        const int ncol = n0 + tx * 8;
        float e[8];
        #pragma unroll
        for (int j = 0; j < 4; j++)
            unpack2(acc2[i][j], e[2 * j], e[2 * j + 1]);
        if (ROPE) {
            const int sp = m & (SS - 1);
            #pragma unroll
            for (int j = 0; j < 8; j += 2) {
                const int pi = ((ncol + j) & (HD - 1)) >> 1;   // pair idx in head
                const float c = cosb[sp * (HD / 2) + pi];
                const float s = sinb[sp * (HD / 2) + pi];
                const float re = e[j];
                const float im = e[j + 1];
                e[j]     = re * c - im * s;
                e[j + 1] = re * s + im * c;
            }
        }
        float* Crow = C + (size_t)m * DD + ncol;
        *(float4*)(Crow)     = make_float4(e[0], e[1], e[2], e[3]);
        *(float4*)(Crow + 4) = make_float4(e[4], e[5], e[6], e[7]);
    }
}

// ---------------------------------------------------------------------------
// Flash attention (causal), fp32 — unchanged (measured 2.0 ms).
// grid = (S/64, B*H). CTA: 64 q-rows, loop over 64-row KV tiles (0..qb).
// ---------------------------------------------------------------------------
#define QT_STRIDE 65
#define V_STRIDE 132
#define SC_STRIDE 65

__global__ __launch_bounds__(256)
void attn_kernel(const float* __restrict__ Q,
                 const float* __restrict__ K,
                 const float* __restrict__ V,
                 float* __restrict__ O)
{
    extern __shared__ float sm[];
    float* qT   = sm;                         // [128][65]  (transposed)
    float* kT   = qT + 128 * QT_STRIDE;       // [128][65]  (transposed)
    float* vs   = kT + 128 * QT_STRIDE;       // [64][132]
    float* sc   = vs + 64 * V_STRIDE;         // [64][65]   scores/probs
    float* m_s  = sc + 64 * SC_STRIDE;        // [64]
    float* l_s  = m_s + 64;                   // [64]
    float* al_s = l_s + 64;                   // [64]

    const int tid = threadIdx.x;
    const int qb  = blockIdx.x;
    const int bh  = blockIdx.y;
    const int b   = bh >> 5;
    const int h   = bh & 31;
    const size_t headoff = (size_t)h * HD;
    const int q0 = qb * 64;

    // load Q tile transposed (coalesced global, conflict-free STS)
    for (int t = tid; t < 64 * 128; t += 256) {
        const int r = t >> 7, d = t & 127;
        qT[d * QT_STRIDE + r] =
            Q[(size_t)(b * SS + q0 + r) * DD + headoff + d];
    }
    if (tid < 64) { m_s[tid] = NEG_INF; l_s[tid] = 0.f; }

    const int tx = tid & 15, ty = tid >> 4;
    const int r0  = ty * 4;      // rows (shared by score + O phases)
    const int c0s = tx * 4;      // score cols

    float o[4][8];               // O col = tx + 16*cc
    #pragma unroll
    for (int i = 0; i < 4; i++)
        #pragma unroll
        for (int cc = 0; cc < 8; cc++) o[i][cc] = 0.f;

    const float scale = 0.088388347648318447f;  // 1/sqrt(128)

    for (int kv = 0; kv <= qb; kv++) {
        const int k0r = kv * 64;
        __syncthreads();   // prior PV done (and Q load on first iter)

        for (int t = tid; t < 64 * 128; t += 256) {
            const int r = t >> 7, d = t & 127;
            const size_t g = (size_t)(b * SS + k0r + r) * DD + headoff + d;
            kT[d * QT_STRIDE + r] = K[g];
            vs[r * V_STRIDE + d]  = V[g];
        }
        __syncthreads();

        // ---- scores: S = Qtile * Ktile^T (64x64), 4x4 per thread
        float s4[4][4];
        #pragma unroll
        for (int i = 0; i < 4; i++)
            #pragma unroll
            for (int j = 0; j < 4; j++) s4[i][j] = 0.f;

        #pragma unroll 4
        for (int kk = 0; kk < 128; kk++) {
            float a[4], bb[4];
            #pragma unroll
            for (int i = 0; i < 4; i++) a[i]  = qT[kk * QT_STRIDE + r0 + i];
            #pragma unroll
            for (int j = 0; j < 4; j++) bb[j] = kT[kk * QT_STRIDE + c0s + j];
            #pragma unroll
            for (int i = 0; i < 4; i++)
                #pragma unroll
                for (int j = 0; j < 4; j++)
                    s4[i][j] += a[i] * bb[j];
        }
        #pragma unroll
        for (int i = 0; i < 4; i++)
            #pragma unroll
            for (int j = 0; j < 4; j++)
                sc[(r0 + i) * SC_STRIDE + c0s + j] = s4[i][j];
        __syncthreads();

        // ---- online softmax: warp w handles rows w*8..w*8+7
        {
            const int wp = tid >> 5, ln = tid & 31;
            const bool diag = (kv == qb);
            for (int rr = 0; rr < 8; rr++) {
                const int r = wp * 8 + rr;
                const int qidx = q0 + r;
                float v0 = sc[r * SC_STRIDE + ln] * scale;
                float v1 = sc[r * SC_STRIDE + 32 + ln] * scale;
                if (diag) {
                    if (k0r + ln > qidx)      v0 = NEG_INF;
                    if (k0r + 32 + ln > qidx) v1 = NEG_INF;
                }
                float mx = fmaxf(v0, v1);
                #pragma unroll
                for (int off = 16; off; off >>= 1)
                    mx = fmaxf(mx, __shfl_xor_sync(0xffffffffu, mx, off));
                const float mold = m_s[r];
                const float mnew = fmaxf(mold, mx);
                const float p0 = __expf(v0 - mnew);
                const float p1 = __expf(v1 - mnew);
                float sum = p0 + p1;
                #pragma unroll
                for (int off = 16; off; off >>= 1)
                    sum += __shfl_xor_sync(0xffffffffu, sum, off);
                sc[r * SC_STRIDE + ln]      = p0;
                sc[r * SC_STRIDE + 32 + ln] = p1;
                if (ln == 0) {
                    const float alpha = __expf(mold - mnew);
                    al_s[r] = alpha;
                    m_s[r]  = mnew;
                    l_s[r]  = l_s[r] * alpha + sum;
                }
            }
        }
        __syncthreads();

        // ---- PV: O = O*alpha + P(64x64) * V(64x128)
        float a4[4];
        #pragma unroll
        for (int i = 0; i < 4; i++) a4[i] = al_s[r0 + i];
        #pragma unroll
        for (int i = 0; i < 4; i++)
            #pragma unroll
            for (int cc = 0; cc < 8; cc++) o[i][cc] *= a4[i];

        #pragma unroll 2
        for (int j = 0; j < 64; j++) {
            float p[4], vv[8];
            #pragma unroll
            for (int i = 0; i < 4; i++) p[i] = sc[(r0 + i) * SC_STRIDE + j];
            #pragma unroll
            for (int cc = 0; cc < 8; cc++) vv[cc] = vs[j * V_STRIDE + tx + 16 * cc];
            #pragma unroll
            for (int i = 0; i < 4; i++)
                #pragma unroll
                for (int cc = 0; cc < 8; cc++)
                    o[i][cc] += p[i] * vv[cc];
        }
    }

    // epilogue: normalize and store (B,S,H,HD) == (B*S, D) row-major
    #pragma unroll
    for (int i = 0; i < 4; i++) {
        const float inv = 1.f / l_s[r0 + i];
        const size_t base = (size_t)(b * SS + q0 + r0 + i) * DD + headoff;
        #pragma unroll
        for (int cc = 0; cc < 8; cc++)
            O[base + tx + 16 * cc] = o[i][cc] * inv;
    }
}

// ---------------------------------------------------------------------------
// kernel_launch
// inputs: 0:x 1:wq 2:wk 3:wv 4:wo 5:freqs_cos 6:freqs_sin 7:mask(unused)
// ---------------------------------------------------------------------------
extern "C" void kernel_launch(void* const* d_in, const int* in_sizes, int n_in,
                              void* d_out, int out_size)
{
    const float* x    = (const float*)d_in[0];
    const float* wq   = (const float*)d_in[1];
    const float* wk   = (const float*)d_in[2];
    const float* wv   = (const float*)d_in[3];
    const float* wo   = (const float*)d_in[4];
    const float* cosb = (const float*)d_in[5];
    const float* sinb = (const float*)d_in[6];
    float* out = (float*)d_out;

    float *pq, *pk, *pv, *pa;
    cudaGetSymbolAddress((void**)&pq, g_q);
    cudaGetSymbolAddress((void**)&pk, g_k);
    cudaGetSymbolAddress((void**)&pv, g_v);
    cudaGetSymbolAddress((void**)&pa, g_attn);

    const int attn_smem = (128 * QT_STRIDE * 2 + 64 * V_STRIDE +
                           64 * SC_STRIDE + 3 * 64) * (int)sizeof(float);
    cudaFuncSetAttribute(attn_kernel,
                         cudaFuncAttributeMaxDynamicSharedMemorySize, attn_smem);

    dim3 ggrid(DD / 128, BS / 128);   // 32 x 32
    dim3 gblk(256);

    gemm_nt_kernel<true ><<<ggrid, gblk>>>(x, wq, pq, cosb, sinb);
    gemm_nt_kernel<true ><<<ggrid, gblk>>>(x, wk, pk, cosb, sinb);
    gemm_nt_kernel<false><<<ggrid, gblk>>>(x, wv, pv, nullptr, nullptr);

    dim3 agrid(SS / 64, BB * HH);     // 16 x 128
    attn_kernel<<<agrid, dim3(256), attn_smem>>>(pq, pk, pv, pa);

    gemm_nt_kernel<false><<<ggrid, gblk>>>(pa, wo, out, nullptr, nullptr);
}